// round 11
// baseline (speedup 1.0000x reference)
#include <cuda_runtime.h>
#include <cuda_fp16.h>

#define NB     8192
#define MAXK   128
#define MAXSID 128
#define NBLK   608
#define NTHR   512
#define PREBLK 32
#define PRETHR 256    // PREBLK*PRETHR == NB, one bucket per thread

// Precomputed tables
__device__ unsigned g_lutU[NB];     // {fp16 b' | u16 cq}  or  {fp16 NaN | sid}
__device__ float4   g_side[MAXSID]; // {t, a_lo, b_lo, b_hi} | all-NaN => >=2 splits
__device__ float    g_sx[MAXK];
__device__ float    g_a[MAXK];
__device__ float    g_b[MAXK];
__device__ float    g_scale, g_offs, g_qbase, g_qstep;

// Bucket map — IDENTICAL expression for data and breakpoints (monotone in x).
__device__ __forceinline__ unsigned bucket_of(float x, float scale, float offs) {
    unsigned b = __float2uint_rz(fmaf(x, scale, offs));   // negatives -> 0
    return min(b, (unsigned)(NB - 1));
}

// ---------------------------------------------------------------------------
// Precompute: 32 blocks x 256 threads (cheap barriers), one bucket/thread.
// Every block redundantly derives sort/scan/quant-range (identical
// deterministic fp ops), then fills its NB/32 slice.
// ---------------------------------------------------------------------------
__global__ void pwl_pre(const float* __restrict__ xp,
                        const float* __restrict__ slopes,
                        const float* __restrict__ biases,
                        int K) {
    __shared__ float s_xp[MAXK], s_sl[MAXK], s_sx[MAXK], s_a[MAXK], s_b[MAXK];
    __shared__ float s_scan[MAXK];
    __shared__ float s_rmin[MAXK], s_rmax[MAXK];
    __shared__ int   s_bb[MAXK], s_iscan[MAXK];
    __shared__ float sh_scale, sh_offs, sh_bias, sh_qbase, sh_qstep;

    const int t = threadIdx.x;

    if (t < K) { s_xp[t] = xp[t]; s_sl[t] = slopes[t]; }
    if (t == 0) sh_bias = biases[0];
    __syncthreads();

    // Stable rank sort, O(K^2) parallel
    if (t < K) {
        float v = s_xp[t];
        int r = 0;
        for (int j = 0; j < K; j++) {
            float w = s_xp[j];
            r += (w < v) || (w == v && j < t);
        }
        s_sx[r] = v;
    }
    __syncthreads();

    // d[i] = (sx[i+1]-sx[i]) * slopes[i]
    if (t < MAXK) {
        float dv = 0.0f;
        if (t < K - 1) dv = (s_sx[t + 1] - s_sx[t]) * s_sl[t];
        s_scan[t] = dv;
    }
    __syncthreads();
    for (int off = 1; off < MAXK; off <<= 1) {      // inclusive Hillis-Steele
        float add = 0.0f;
        if (t < MAXK && t >= off) add = s_scan[t - off];
        __syncthreads();
        if (t < MAXK) s_scan[t] += add;
        __syncthreads();
    }
    // beta[i] = bias + cum[i-1];  a[i] = beta[i] - sx[i]*b[i]
    if (t < MAXK) {
        float beta = sh_bias + (t > 0 ? s_scan[t - 1] : 0.0f);
        if (t < K) {
            s_b[t] = s_sl[t];
            s_a[t] = fmaf(-s_sx[t], s_sl[t], beta);
        }
        s_rmin[t] = (t < K) ? beta :  3.4e38f;
        s_rmax[t] = (t < K) ? beta : -3.4e38f;
    }
    if (t == 0) {
        float range = s_sx[K - 1] - s_sx[0];
        sh_scale = (range > 0.0f) ? (float)NB / range : 0.0f;
        sh_offs  = -s_sx[0] * sh_scale;
    }
    __syncthreads();
    for (int off = MAXK / 2; off > 0; off >>= 1) {  // min/max tree reduce
        if (t < off) {
            s_rmin[t] = fminf(s_rmin[t], s_rmin[t + off]);
            s_rmax[t] = fmaxf(s_rmax[t], s_rmax[t + off]);
        }
        __syncthreads();
    }
    if (t == 0) {
        float qr = s_rmax[0] - s_rmin[0];
        sh_qbase = s_rmin[0];
        sh_qstep = (qr > 0.0f) ? qr / 65535.0f : 1.0f;
        if (blockIdx.x == 0) {
            g_scale = sh_scale; g_offs = sh_offs;
            g_qbase = sh_qbase; g_qstep = sh_qstep;
        }
    }
    __syncthreads();
    const float scale = sh_scale, offs = sh_offs;
    const float qbase = sh_qbase, qstep = sh_qstep;

    if (t < K) s_bb[t] = (int)bucket_of(s_sx[t], scale, offs);   // monotone
    __syncthreads();

    // sid rank: flag[j]=1 if j>=1 starts a new distinct flagged bucket
    if (t < MAXK) {
        int f = 0;
        if (t >= 1 && t < K) f = (t == 1) || (s_bb[t] != s_bb[t - 1]);
        s_iscan[t] = f;
    }
    __syncthreads();
    for (int off = 1; off < MAXK; off <<= 1) {
        int add = 0;
        if (t < MAXK && t >= off) add = s_iscan[t - off];
        __syncthreads();
        if (t < MAXK) s_iscan[t] += add;
        __syncthreads();
    }

    const float QNAN = __int_as_float(0x7FC00000);
    const float INF  = __int_as_float(0x7F800000);
    const int   bkt  = blockIdx.x * PRETHR + t;     // 32*256 = 8192

    // pl = #{j: bb[j] < bkt}, c = #{j: bb[j] == bkt} via binary search
    int lo = 0, hi = K;
    while (lo < hi) { int m = (lo + hi) >> 1; if (s_bb[m] < bkt) lo = m + 1; else hi = m; }
    const int pl = lo;
    hi = K;
    while (lo < hi) { int m = (lo + hi) >> 1; if (s_bb[m] <= bkt) lo = m + 1; else hi = m; }
    const int c = lo - pl;
    const int idx0 = min(max(pl, 1), K) - 1;

    // Effective (post-clip, equal-threshold-merged) transitions in bucket
    int   cur = idx0, eff = 0, g0 = idx0, g1 = idx0;
    float t1 = INF, lastthr = 0.0f;
    for (int tt = 1; tt <= c; tt++) {
        int   ni  = min(max(pl + tt, 1), K) - 1;
        float thr = s_sx[pl + tt - 1];
        if (ni == cur) continue;
        if (eff >= 1 && thr == lastthr) {
            if (eff == 1) g1 = ni;
        } else {
            eff++;
            lastthr = thr;
            if (eff == 1) { t1 = thr; g1 = ni; }
        }
        cur = ni;
    }

    if (eff == 0) {
        // c_left = PWL at bucket left edge; b' = b/scale (grid units)
        float x_left = ((float)bkt - offs) / scale;       // scale==0 never read
        float cl = fmaf(s_b[idx0], x_left, s_a[idx0]);
        int cq = __float2int_rn((cl - qbase) / qstep);
        cq = min(max(cq, 0), 65535);
        unsigned short bh = __half_as_ushort(__float2half_rn(s_b[idx0] / scale));
        g_lutU[bkt] = ((unsigned)bh << 16) | (unsigned)cq;
    } else {
        int jf  = max(pl, 1);
        int sid = min(max(s_iscan[jf] - 1, 0), MAXSID - 1);
        g_lutU[bkt] = (0x7E00u << 16) | (unsigned)sid;    // fp16 NaN | sid
        if (eff == 1) {
            g_side[sid] = make_float4(t1, s_a[g0], s_b[g0], s_b[g1]);
        } else {
            g_side[sid] = make_float4(QNAN, QNAN, QNAN, QNAN);
        }
    }

    if (blockIdx.x == 0 && t < K) {
        g_sx[t] = s_sx[t];
        g_a[t]  = s_a[t];
        g_b[t]  = s_b[t];
    }
}

// ---------------------------------------------------------------------------
// Main kernel
// ---------------------------------------------------------------------------

// Flagged resolve: ONE LDS.128 + selects; exact fp32. Safe for inactive lanes.
__device__ __forceinline__ float side_raw(bool on, float x, unsigned e, float old,
                                          const float4* __restrict__ s_side) {
    int sid = (int)(e & 0xFFFFu);
    sid = min(sid, MAXSID - 1);
    float4 A = s_side[sid];                        // {t, a_lo, b_lo, b_hi}
    bool  ge = (x >= A.x);                         // false for NaN record
    float bb = ge ? A.w : A.z;
    float aa = ge ? fmaf(A.x, A.z - A.w, A.y) : A.y;
    float y  = fmaf(bb, x, aa);                    // NaN record -> NaN
    return on ? y : old;
}

__device__ __noinline__ float search_eval(float x,
                                          const float* __restrict__ s_sx,
                                          const float* __restrict__ s_a,
                                          const float* __restrict__ s_b,
                                          int K) {
    int lo = 0, hi = K;
    while (lo < hi) {
        int mid = (lo + hi) >> 1;
        if (s_sx[mid] <= x) lo = mid + 1; else hi = mid;
    }
    int idx = min(max(lo, 1), K) - 1;
    return fmaf(s_b[idx], x, s_a[idx]);
}

// Decode one element: 4-byte entry, single-phase LDS.32 gather.
__device__ __forceinline__ float pwl_dec(float x, float scale, float offs,
                                         float qbase, float qstep,
                                         const unsigned* __restrict__ s_lut,
                                         unsigned& e_out) {
    float gf = fmaf(x, scale, offs);
    unsigned bi = min(__float2uint_rz(gf), (unsigned)(NB - 1));
    unsigned e = s_lut[bi];
    e_out = e;
    float frac = gf - (float)bi;                   // bucket-local coordinate
    float cc = fmaf((float)(e & 0xFFFFu), qstep, qbase);
    float bw = __half2float(__ushort_as_half((unsigned short)(e >> 16)));
    return fmaf(bw, frac, cc);                     // NaN if flagged
}

// Resolve flagged/cold lanes then saturate. u is non-NaN at saturate time.
__device__ __forceinline__ float finish(float u, float xv, unsigned e,
                                        const float4* __restrict__ s_side,
                                        const float*  __restrict__ s_sx,
                                        const float*  __restrict__ s_a,
                                        const float*  __restrict__ s_b, int K) {
    return __saturatef(u);
}

__global__ void __launch_bounds__(NTHR, 4)
pwl_main(const float* __restrict__ x, float* __restrict__ out, int n, int K) {
    __shared__ unsigned s_lut[NB];
    __shared__ float4   s_side[MAXSID];
    __shared__ float    s_sx[MAXK], s_a[MAXK], s_b[MAXK];

    {   // stage LUT with uint4 loads
        const uint4* src = (const uint4*)g_lutU;
        uint4* dst = (uint4*)s_lut;
        for (int i = threadIdx.x; i < NB / 4; i += NTHR) dst[i] = src[i];
        if (threadIdx.x < MAXSID) s_side[threadIdx.x] = g_side[threadIdx.x];
        if (threadIdx.x < MAXK) {
            int i = threadIdx.x;
            s_sx[i] = g_sx[i]; s_a[i] = g_a[i]; s_b[i] = g_b[i];
        }
    }
    __syncthreads();

    const float scale = g_scale, offs = g_offs;
    const float qbase = g_qbase, qstep = g_qstep;
    const int n4 = n >> 2;
    const float4* __restrict__ x4 = (const float4*)x;
    float4* __restrict__ o4 = (float4*)out;
    const int stride2 = gridDim.x * NTHR * 2;

    // 8 elements (2 coalesced float4s) per thread per iteration.
    for (int i = blockIdx.x * (NTHR * 2) + threadIdx.x; i < n4; i += stride2) {
        const int  j  = i + NTHR;
        const bool hj = (j < n4);
        float4 v = x4[i];
        float4 w = hj ? x4[j] : make_float4(0.f, 0.f, 0.f, 0.f);

        unsigned e0, e1, e2, e3, e4, e5, e6, e7;
        float u0 = pwl_dec(v.x, scale, offs, qbase, qstep, s_lut, e0);
        float u1 = pwl_dec(v.y, scale, offs, qbase, qstep, s_lut, e1);
        float u2 = pwl_dec(v.z, scale, offs, qbase, qstep, s_lut, e2);
        float u3 = pwl_dec(v.w, scale, offs, qbase, qstep, s_lut, e3);
        float u4 = pwl_dec(w.x, scale, offs, qbase, qstep, s_lut, e4);
        float u5 = pwl_dec(w.y, scale, offs, qbase, qstep, s_lut, e5);
        float u6 = pwl_dec(w.z, scale, offs, qbase, qstep, s_lut, e6);
        float u7 = pwl_dec(w.w, scale, offs, qbase, qstep, s_lut, e7);

        bool f0 = (u0 != u0), f1 = (u1 != u1), f2 = (u2 != u2), f3 = (u3 != u3);
        bool f4 = (u4 != u4), f5 = (u5 != u5), f6 = (u6 != u6), f7 = (u7 != u7);
        if (f0 | f1 | f2 | f3 | f4 | f5 | f6 | f7) {       // hot branch
            u0 = side_raw(f0, v.x, e0, u0, s_side);
            u1 = side_raw(f1, v.y, e1, u1, s_side);
            u2 = side_raw(f2, v.z, e2, u2, s_side);
            u3 = side_raw(f3, v.w, e3, u3, s_side);
            u4 = side_raw(f4, w.x, e4, u4, s_side);
            u5 = side_raw(f5, w.y, e5, u5, s_side);
            u6 = side_raw(f6, w.z, e6, u6, s_side);
            u7 = side_raw(f7, w.w, e7, u7, s_side);
            if ((u0 != u0) | (u1 != u1) | (u2 != u2) | (u3 != u3) |
                (u4 != u4) | (u5 != u5) | (u6 != u6) | (u7 != u7)) {  // cold
                if (u0 != u0) u0 = search_eval(v.x, s_sx, s_a, s_b, K);
                if (u1 != u1) u1 = search_eval(v.y, s_sx, s_a, s_b, K);
                if (u2 != u2) u2 = search_eval(v.z, s_sx, s_a, s_b, K);
                if (u3 != u3) u3 = search_eval(v.w, s_sx, s_a, s_b, K);
                if (u4 != u4) u4 = search_eval(w.x, s_sx, s_a, s_b, K);
                if (u5 != u5) u5 = search_eval(w.y, s_sx, s_a, s_b, K);
                if (u6 != u6) u6 = search_eval(w.z, s_sx, s_a, s_b, K);
                if (u7 != u7) u7 = search_eval(w.w, s_sx, s_a, s_b, K);
            }
        }

        float4 r;
        r.x = __saturatef(u0); r.y = __saturatef(u1);
        r.z = __saturatef(u2); r.w = __saturatef(u3);
        o4[i] = r;
        if (hj) {
            float4 s;
            s.x = __saturatef(u4); s.y = __saturatef(u5);
            s.z = __saturatef(u6); s.w = __saturatef(u7);
            o4[j] = s;
        }
    }

    // Scalar tail
    int rem = n & 3;
    if (blockIdx.x == 0 && (int)threadIdx.x < rem) {
        int i = (n4 << 2) + threadIdx.x;
        float xv = x[i];
        unsigned e;
        float u = pwl_dec(xv, scale, offs, qbase, qstep, s_lut, e);
        if (u != u) {
            u = side_raw(true, xv, e, u, s_side);
            if (u != u) u = search_eval(xv, s_sx, s_a, s_b, K);
        }
        out[i] = __saturatef(u);
    }
}

// ---------------------------------------------------------------------------
extern "C" void kernel_launch(void* const* d_in, const int* in_sizes, int n_in,
                              void* d_out, int out_size) {
    const float* x      = (const float*)d_in[0];
    const float* xp     = (const float*)d_in[1];
    const float* slopes = (const float*)d_in[2];
    const float* biases = (const float*)d_in[3];
    int K = in_sizes[1];
    if (K > MAXK) K = MAXK;

    pwl_pre<<<PREBLK, PRETHR>>>(xp, slopes, biases, K);
    pwl_main<<<NBLK, NTHR>>>(x, (float*)d_out, out_size, K);
}

// round 14
// speedup vs baseline: 1.0660x; 1.0660x over previous
#include <cuda_runtime.h>
#include <cuda_fp16.h>

#define NB     8192
#define MAXK   128
#define MAXSID 128
#define NBLK   608
#define NTHR   512
#define PREBLK 32
#define PRETHR 256    // PREBLK*PRETHR == NB, one bucket per thread

// Precomputed tables
__device__ unsigned g_lutU[NB];     // {fp16 b' | u16 cq}  or  {fp16 NaN | sid}
__device__ float4   g_side[MAXSID]; // {t, a_lo, b_lo, b_hi} | all-NaN => >=2 splits
__device__ float    g_sx[MAXK];
__device__ float    g_a[MAXK];
__device__ float    g_b[MAXK];
__device__ float    g_scale, g_offs, g_qbase, g_qstep;

// Bucket map — IDENTICAL expression for data and breakpoints (monotone in x).
__device__ __forceinline__ unsigned bucket_of(float x, float scale, float offs) {
    unsigned b = __float2uint_rz(fmaf(x, scale, offs));   // negatives -> 0
    return min(b, (unsigned)(NB - 1));
}

// ---------------------------------------------------------------------------
// Precompute: 32 blocks x 256 threads (cheap barriers), one bucket/thread.
// Every block redundantly derives sort/scan/quant-range (identical
// deterministic fp ops), then fills its NB/32 slice.
// ---------------------------------------------------------------------------
__global__ void pwl_pre(const float* __restrict__ xp,
                        const float* __restrict__ slopes,
                        const float* __restrict__ biases,
                        int K) {
    __shared__ float s_xp[MAXK], s_sl[MAXK], s_sx[MAXK], s_a[MAXK], s_b[MAXK];
    __shared__ float s_scan[MAXK];
    __shared__ float s_rmin[MAXK], s_rmax[MAXK];
    __shared__ int   s_bb[MAXK], s_iscan[MAXK];
    __shared__ float sh_scale, sh_offs, sh_bias, sh_qbase, sh_qstep;

    const int t = threadIdx.x;

    if (t < K) { s_xp[t] = xp[t]; s_sl[t] = slopes[t]; }
    if (t == 0) sh_bias = biases[0];
    __syncthreads();

    // Stable rank sort, O(K^2) parallel
    if (t < K) {
        float v = s_xp[t];
        int r = 0;
        for (int j = 0; j < K; j++) {
            float w = s_xp[j];
            r += (w < v) || (w == v && j < t);
        }
        s_sx[r] = v;
    }
    __syncthreads();

    // d[i] = (sx[i+1]-sx[i]) * slopes[i]
    if (t < MAXK) {
        float dv = 0.0f;
        if (t < K - 1) dv = (s_sx[t + 1] - s_sx[t]) * s_sl[t];
        s_scan[t] = dv;
    }
    __syncthreads();
    for (int off = 1; off < MAXK; off <<= 1) {      // inclusive Hillis-Steele
        float add = 0.0f;
        if (t < MAXK && t >= off) add = s_scan[t - off];
        __syncthreads();
        if (t < MAXK) s_scan[t] += add;
        __syncthreads();
    }
    // beta[i] = bias + cum[i-1];  a[i] = beta[i] - sx[i]*b[i]
    if (t < MAXK) {
        float beta = sh_bias + (t > 0 ? s_scan[t - 1] : 0.0f);
        if (t < K) {
            s_b[t] = s_sl[t];
            s_a[t] = fmaf(-s_sx[t], s_sl[t], beta);
        }
        s_rmin[t] = (t < K) ? beta :  3.4e38f;
        s_rmax[t] = (t < K) ? beta : -3.4e38f;
    }
    if (t == 0) {
        float range = s_sx[K - 1] - s_sx[0];
        sh_scale = (range > 0.0f) ? (float)NB / range : 0.0f;
        sh_offs  = -s_sx[0] * sh_scale;
    }
    __syncthreads();
    for (int off = MAXK / 2; off > 0; off >>= 1) {  // min/max tree reduce
        if (t < off) {
            s_rmin[t] = fminf(s_rmin[t], s_rmin[t + off]);
            s_rmax[t] = fmaxf(s_rmax[t], s_rmax[t + off]);
        }
        __syncthreads();
    }
    if (t == 0) {
        float qr = s_rmax[0] - s_rmin[0];
        sh_qbase = s_rmin[0];
        sh_qstep = (qr > 0.0f) ? qr / 65535.0f : 1.0f;
        if (blockIdx.x == 0) {
            g_scale = sh_scale; g_offs = sh_offs;
            g_qbase = sh_qbase; g_qstep = sh_qstep;
        }
    }
    __syncthreads();
    const float scale = sh_scale, offs = sh_offs;
    const float qbase = sh_qbase, qstep = sh_qstep;

    if (t < K) s_bb[t] = (int)bucket_of(s_sx[t], scale, offs);   // monotone
    __syncthreads();

    // sid rank: flag[j]=1 if j>=1 starts a new distinct flagged bucket
    if (t < MAXK) {
        int f = 0;
        if (t >= 1 && t < K) f = (t == 1) || (s_bb[t] != s_bb[t - 1]);
        s_iscan[t] = f;
    }
    __syncthreads();
    for (int off = 1; off < MAXK; off <<= 1) {
        int add = 0;
        if (t < MAXK && t >= off) add = s_iscan[t - off];
        __syncthreads();
        if (t < MAXK) s_iscan[t] += add;
        __syncthreads();
    }

    const float QNAN = __int_as_float(0x7FC00000);
    const float INF  = __int_as_float(0x7F800000);
    const int   bkt  = blockIdx.x * PRETHR + t;     // 32*256 = 8192

    // pl = #{j: bb[j] < bkt}, c = #{j: bb[j] == bkt} via binary search
    int lo = 0, hi = K;
    while (lo < hi) { int m = (lo + hi) >> 1; if (s_bb[m] < bkt) lo = m + 1; else hi = m; }
    const int pl = lo;
    hi = K;
    while (lo < hi) { int m = (lo + hi) >> 1; if (s_bb[m] <= bkt) lo = m + 1; else hi = m; }
    const int c = lo - pl;
    const int idx0 = min(max(pl, 1), K) - 1;

    // Effective (post-clip, equal-threshold-merged) transitions in bucket
    int   cur = idx0, eff = 0, g0 = idx0, g1 = idx0;
    float t1 = INF, lastthr = 0.0f;
    for (int tt = 1; tt <= c; tt++) {
        int   ni  = min(max(pl + tt, 1), K) - 1;
        float thr = s_sx[pl + tt - 1];
        if (ni == cur) continue;
        if (eff >= 1 && thr == lastthr) {
            if (eff == 1) g1 = ni;
        } else {
            eff++;
            lastthr = thr;
            if (eff == 1) { t1 = thr; g1 = ni; }
        }
        cur = ni;
    }

    if (eff == 0) {
        // c_left = PWL at bucket left edge; b' = b/scale (grid units)
        float x_left = ((float)bkt - offs) / scale;       // scale==0 never read
        float cl = fmaf(s_b[idx0], x_left, s_a[idx0]);
        int cq = __float2int_rn((cl - qbase) / qstep);
        cq = min(max(cq, 0), 65535);
        unsigned short bh = __half_as_ushort(__float2half_rn(s_b[idx0] / scale));
        g_lutU[bkt] = ((unsigned)bh << 16) | (unsigned)cq;
    } else {
        int jf  = max(pl, 1);
        int sid = min(max(s_iscan[jf] - 1, 0), MAXSID - 1);
        g_lutU[bkt] = (0x7E00u << 16) | (unsigned)sid;    // fp16 NaN | sid
        if (eff == 1) {
            g_side[sid] = make_float4(t1, s_a[g0], s_b[g0], s_b[g1]);
        } else {
            g_side[sid] = make_float4(QNAN, QNAN, QNAN, QNAN);
        }
    }

    if (blockIdx.x == 0 && t < K) {
        g_sx[t] = s_sx[t];
        g_a[t]  = s_a[t];
        g_b[t]  = s_b[t];
    }
}

// ---------------------------------------------------------------------------
// Main kernel
// ---------------------------------------------------------------------------

// Flagged resolve: ONE LDS.128 + selects; exact fp32. Safe for inactive lanes.
__device__ __forceinline__ float side_raw(bool on, float x, unsigned e, float old,
                                          const float4* __restrict__ s_side) {
    int sid = (int)(e & 0xFFFFu);
    sid = min(sid, MAXSID - 1);
    float4 A = s_side[sid];                        // {t, a_lo, b_lo, b_hi}
    bool  ge = (x >= A.x);                         // false for NaN record
    float bb = ge ? A.w : A.z;
    float aa = ge ? fmaf(A.x, A.z - A.w, A.y) : A.y;
    float y  = fmaf(bb, x, aa);                    // NaN record -> NaN
    return on ? y : old;
}

__device__ __noinline__ float search_eval(float x,
                                          const float* __restrict__ s_sx,
                                          const float* __restrict__ s_a,
                                          const float* __restrict__ s_b,
                                          int K) {
    int lo = 0, hi = K;
    while (lo < hi) {
        int mid = (lo + hi) >> 1;
        if (s_sx[mid] <= x) lo = mid + 1; else hi = mid;
    }
    int idx = min(max(lo, 1), K) - 1;
    return fmaf(s_b[idx], x, s_a[idx]);
}

// Decode one element: 4-byte entry, single-phase LDS.32 gather.
__device__ __forceinline__ float pwl_dec(float x, float scale, float offs,
                                         float qbase, float qstep,
                                         const unsigned* __restrict__ s_lut,
                                         unsigned& e_out) {
    float gf = fmaf(x, scale, offs);
    unsigned bi = min(__float2uint_rz(gf), (unsigned)(NB - 1));
    unsigned e = s_lut[bi];
    e_out = e;
    float frac = gf - (float)bi;                   // bucket-local coordinate
    float cc = fmaf((float)(e & 0xFFFFu), qstep, qbase);
    float bw = __half2float(__ushort_as_half((unsigned short)(e >> 16)));
    return fmaf(bw, frac, cc);                     // NaN if flagged
}

__global__ void __launch_bounds__(NTHR, 4)
pwl_main(const float* __restrict__ x, float* __restrict__ out, int n, int K) {
    __shared__ unsigned s_lut[NB];
    __shared__ float4   s_side[MAXSID];
    __shared__ float    s_sx[MAXK], s_a[MAXK], s_b[MAXK];

    {   // stage LUT with uint4 loads
        const uint4* src = (const uint4*)g_lutU;
        uint4* dst = (uint4*)s_lut;
        for (int i = threadIdx.x; i < NB / 4; i += NTHR) dst[i] = src[i];
        if (threadIdx.x < MAXSID) s_side[threadIdx.x] = g_side[threadIdx.x];
        if (threadIdx.x < MAXK) {
            int i = threadIdx.x;
            s_sx[i] = g_sx[i]; s_a[i] = g_a[i]; s_b[i] = g_b[i];
        }
    }
    __syncthreads();

    const float scale = g_scale, offs = g_offs;
    const float qbase = g_qbase, qstep = g_qstep;
    const int n4 = n >> 2;
    const float4* __restrict__ x4 = (const float4*)x;
    float4* __restrict__ o4 = (float4*)out;
    const int stride = gridDim.x * NTHR;

    #pragma unroll 2
    for (int i = blockIdx.x * NTHR + threadIdx.x; i < n4; i += stride) {
        float4 v = x4[i];
        unsigned e0, e1, e2, e3;
        float u0 = pwl_dec(v.x, scale, offs, qbase, qstep, s_lut, e0);
        float u1 = pwl_dec(v.y, scale, offs, qbase, qstep, s_lut, e1);
        float u2 = pwl_dec(v.z, scale, offs, qbase, qstep, s_lut, e2);
        float u3 = pwl_dec(v.w, scale, offs, qbase, qstep, s_lut, e3);

        bool f0 = (u0 != u0), f1 = (u1 != u1), f2 = (u2 != u2), f3 = (u3 != u3);
        if (f0 | f1 | f2 | f3) {                   // hot branch, slim body
            u0 = side_raw(f0, v.x, e0, u0, s_side);
            u1 = side_raw(f1, v.y, e1, u1, s_side);
            u2 = side_raw(f2, v.z, e2, u2, s_side);
            u3 = side_raw(f3, v.w, e3, u3, s_side);
            if ((u0 != u0) | (u1 != u1) | (u2 != u2) | (u3 != u3)) {  // cold
                if (u0 != u0) u0 = search_eval(v.x, s_sx, s_a, s_b, K);
                if (u1 != u1) u1 = search_eval(v.y, s_sx, s_a, s_b, K);
                if (u2 != u2) u2 = search_eval(v.z, s_sx, s_a, s_b, K);
                if (u3 != u3) u3 = search_eval(v.w, s_sx, s_a, s_b, K);
            }
        }

        float4 r;
        r.x = __saturatef(u0);
        r.y = __saturatef(u1);
        r.z = __saturatef(u2);
        r.w = __saturatef(u3);
        o4[i] = r;
    }

    // Scalar tail
    int rem = n & 3;
    if (blockIdx.x == 0 && (int)threadIdx.x < rem) {
        int i = (n4 << 2) + threadIdx.x;
        float xv = x[i];
        unsigned e;
        float u = pwl_dec(xv, scale, offs, qbase, qstep, s_lut, e);
        if (u != u) {
            u = side_raw(true, xv, e, u, s_side);
            if (u != u) u = search_eval(xv, s_sx, s_a, s_b, K);
        }
        out[i] = __saturatef(u);
    }
}

// ---------------------------------------------------------------------------
extern "C" void kernel_launch(void* const* d_in, const int* in_sizes, int n_in,
                              void* d_out, int out_size) {
    const float* x      = (const float*)d_in[0];
    const float* xp     = (const float*)d_in[1];
    const float* slopes = (const float*)d_in[2];
    const float* biases = (const float*)d_in[3];
    int K = in_sizes[1];
    if (K > MAXK) K = MAXK;

    pwl_pre<<<PREBLK, PRETHR>>>(xp, slopes, biases, K);
    pwl_main<<<NBLK, NTHR>>>(x, (float*)d_out, out_size, K);
}

// round 15
// speedup vs baseline: 1.0752x; 1.0087x over previous
#include <cuda_runtime.h>
#include <cuda_fp16.h>

#define NB     8192
#define MAXK   128
#define MAXSID 128
#define NBLK   608
#define NTHR   512
#define PREBLK 32
#define PRETHR 256    // PREBLK*PRETHR == NB, one bucket per thread

// Precomputed tables
__device__ unsigned g_lutU[NB];     // {fp16 b | u16 cq}  or  {fp16 NaN | sid(<128)}
__device__ float4   g_side[MAXSID]; // {t, a_lo, b_lo, b_hi} | all-NaN => >=2 splits
__device__ float    g_sx[MAXK];
__device__ float    g_a[MAXK];
__device__ float    g_b[MAXK];
__device__ float    g_scale, g_offs, g_qbase, g_qstep;

// Bucket map — IDENTICAL expression for data and breakpoints (monotone in x).
__device__ __forceinline__ unsigned bucket_of(float x, float scale, float offs) {
    unsigned b = __float2uint_rz(fmaf(x, scale, offs));   // negatives -> 0
    return min(b, (unsigned)(NB - 1));
}

// ---------------------------------------------------------------------------
// Precompute: 32 blocks x 256 threads, one bucket/thread. Every block
// redundantly derives sort/scan/quant-range (identical deterministic fp ops),
// then fills its NB/32 slice.
// ---------------------------------------------------------------------------
__global__ void pwl_pre(const float* __restrict__ xp,
                        const float* __restrict__ slopes,
                        const float* __restrict__ biases,
                        int K) {
    __shared__ float s_xp[MAXK], s_sl[MAXK], s_sx[MAXK], s_a[MAXK], s_b[MAXK];
    __shared__ float s_scan[MAXK];
    __shared__ float s_rmin[MAXK], s_rmax[MAXK], s_bmax[MAXK];
    __shared__ int   s_bb[MAXK], s_iscan[MAXK];
    __shared__ float sh_scale, sh_offs, sh_bias, sh_qbase, sh_qstep;

    const int t = threadIdx.x;

    if (t < K) { s_xp[t] = xp[t]; s_sl[t] = slopes[t]; }
    if (t == 0) sh_bias = biases[0];
    __syncthreads();

    // Stable rank sort, O(K^2) parallel
    if (t < K) {
        float v = s_xp[t];
        int r = 0;
        for (int j = 0; j < K; j++) {
            float w = s_xp[j];
            r += (w < v) || (w == v && j < t);
        }
        s_sx[r] = v;
    }
    __syncthreads();

    // d[i] = (sx[i+1]-sx[i]) * slopes[i]
    if (t < MAXK) {
        float dv = 0.0f;
        if (t < K - 1) dv = (s_sx[t + 1] - s_sx[t]) * s_sl[t];
        s_scan[t] = dv;
    }
    __syncthreads();
    for (int off = 1; off < MAXK; off <<= 1) {      // inclusive Hillis-Steele
        float add = 0.0f;
        if (t < MAXK && t >= off) add = s_scan[t - off];
        __syncthreads();
        if (t < MAXK) s_scan[t] += add;
        __syncthreads();
    }
    // beta[i] = bias + cum[i-1];  a[i] = beta[i] - sx[i]*b[i]
    if (t < MAXK) {
        float beta = sh_bias + (t > 0 ? s_scan[t - 1] : 0.0f);
        float av = 0.0f, bv = 0.0f;
        if (t < K) {
            bv = s_sl[t];
            av = fmaf(-s_sx[t], bv, beta);
            s_b[t] = bv;
            s_a[t] = av;
        }
        // quantization range covers c = a + (b - fp16(b))*x_left  ~= a +/- delta
        s_rmin[t] = (t < K) ? av :  3.4e38f;
        s_rmax[t] = (t < K) ? av : -3.4e38f;
        s_bmax[t] = (t < K) ? fabsf(bv) : 0.0f;
    }
    if (t == 0) {
        float range = s_sx[K - 1] - s_sx[0];
        sh_scale = (range > 0.0f) ? (float)NB / range : 0.0f;
        sh_offs  = -s_sx[0] * sh_scale;
    }
    __syncthreads();
    for (int off = MAXK / 2; off > 0; off >>= 1) {  // min/max tree reduce
        if (t < off) {
            s_rmin[t] = fminf(s_rmin[t], s_rmin[t + off]);
            s_rmax[t] = fmaxf(s_rmax[t], s_rmax[t + off]);
            s_bmax[t] = fmaxf(s_bmax[t], s_bmax[t + off]);
        }
        __syncthreads();
    }
    if (t == 0) {
        float xmax  = fmaxf(fabsf(s_sx[0]), fabsf(s_sx[K - 1]));
        float delta = s_bmax[0] * xmax * 4.8828125e-4f;   // 2^-11, safety x margin
        float qb = s_rmin[0] - delta;
        float qr = (s_rmax[0] - s_rmin[0]) + 2.0f * delta;
        sh_qbase = qb;
        sh_qstep = (qr > 0.0f) ? qr / 65535.0f : 1.0f;
        if (blockIdx.x == 0) {
            g_scale = sh_scale; g_offs = sh_offs;
            g_qbase = sh_qbase; g_qstep = sh_qstep;
        }
    }
    __syncthreads();
    const float scale = sh_scale, offs = sh_offs;
    const float qbase = sh_qbase, qstep = sh_qstep;

    if (t < K) s_bb[t] = (int)bucket_of(s_sx[t], scale, offs);   // monotone
    __syncthreads();

    // sid rank: flag[j]=1 if j>=1 starts a new distinct flagged bucket
    if (t < MAXK) {
        int f = 0;
        if (t >= 1 && t < K) f = (t == 1) || (s_bb[t] != s_bb[t - 1]);
        s_iscan[t] = f;
    }
    __syncthreads();
    for (int off = 1; off < MAXK; off <<= 1) {
        int add = 0;
        if (t < MAXK && t >= off) add = s_iscan[t - off];
        __syncthreads();
        if (t < MAXK) s_iscan[t] += add;
        __syncthreads();
    }

    const float QNAN = __int_as_float(0x7FC00000);
    const float INF  = __int_as_float(0x7F800000);
    const int   bkt  = blockIdx.x * PRETHR + t;     // 32*256 = 8192

    // pl = #{j: bb[j] < bkt}, c = #{j: bb[j] == bkt} via binary search
    int lo = 0, hi = K;
    while (lo < hi) { int m = (lo + hi) >> 1; if (s_bb[m] < bkt) lo = m + 1; else hi = m; }
    const int pl = lo;
    hi = K;
    while (lo < hi) { int m = (lo + hi) >> 1; if (s_bb[m] <= bkt) lo = m + 1; else hi = m; }
    const int c = lo - pl;
    const int idx0 = min(max(pl, 1), K) - 1;

    // Effective (post-clip, equal-threshold-merged) transitions in bucket
    int   cur = idx0, eff = 0, g0 = idx0, g1 = idx0;
    float t1 = INF, lastthr = 0.0f;
    for (int tt = 1; tt <= c; tt++) {
        int   ni  = min(max(pl + tt, 1), K) - 1;
        float thr = s_sx[pl + tt - 1];
        if (ni == cur) continue;
        if (eff >= 1 && thr == lastthr) {
            if (eff == 1) g1 = ni;
        } else {
            eff++;
            lastthr = thr;
            if (eff == 1) { t1 = thr; g1 = ni; }
        }
        cur = ni;
    }

    if (eff == 0) {
        // Encode y = bwf*x + cc with bwf = fp16(b); cc exact at x_left.
        float bfull = s_b[idx0];
        unsigned short bh = __half_as_ushort(__float2half_rn(bfull));
        float bwf = __half2float(__ushort_as_half(bh));
        float x_left = ((float)bkt - offs) / scale;       // ref point in bucket
        float cv = fmaf(bfull - bwf, x_left, s_a[idx0]);  // c = a + (b-bwf)*x_left
        int cq = __float2int_rn((cv - qbase) / qstep);
        cq = min(max(cq, 0), 65535);
        g_lutU[bkt] = ((unsigned)bh << 16) | (unsigned)cq;
    } else {
        int jf  = max(pl, 1);
        int sid = min(max(s_iscan[jf] - 1, 0), MAXSID - 1);   // < 128 guaranteed
        g_lutU[bkt] = (0x7E00u << 16) | (unsigned)sid;        // fp16 NaN | sid
        if (eff == 1) {
            g_side[sid] = make_float4(t1, s_a[g0], s_b[g0], s_b[g1]);
        } else {
            g_side[sid] = make_float4(QNAN, QNAN, QNAN, QNAN);
        }
    }

    if (blockIdx.x == 0 && t < K) {
        g_sx[t] = s_sx[t];
        g_a[t]  = s_a[t];
        g_b[t]  = s_b[t];
    }
}

// ---------------------------------------------------------------------------
// Main kernel
// ---------------------------------------------------------------------------

// Flagged resolve: ONE LDS.128 + selects; exact fp32. sid stored < 128 so a
// single AND 0x7F is a safe index for predicated-off (clean-entry) lanes.
__device__ __forceinline__ float side_raw(bool on, float x, unsigned e, float old,
                                          const float4* __restrict__ s_side) {
    int sid = (int)(e & 0x7Fu);
    float4 A = s_side[sid];                        // {t, a_lo, b_lo, b_hi}
    bool  ge = (x >= A.x);                         // false for NaN record
    float bb = ge ? A.w : A.z;
    float aa = ge ? fmaf(A.x, A.z - A.w, A.y) : A.y;
    float y  = fmaf(bb, x, aa);                    // NaN record -> NaN
    return on ? y : old;
}

__device__ __noinline__ float search_eval(float x,
                                          const float* __restrict__ s_sx,
                                          const float* __restrict__ s_a,
                                          const float* __restrict__ s_b,
                                          int K) {
    int lo = 0, hi = K;
    while (lo < hi) {
        int mid = (lo + hi) >> 1;
        if (s_sx[mid] <= x) lo = mid + 1; else hi = mid;
    }
    int idx = min(max(lo, 1), K) - 1;
    return fmaf(s_b[idx], x, s_a[idx]);
}

// Decode one element. Hot path: FFMA, F2U, IMNMX, LDS.32, AND+I2F+FFMA (cc),
// SHF+F2F (bw), FSETP (flag), FFMA.SAT (y). No frac, no separate clamp.
__device__ __forceinline__ float pwl_dec(float x, float scale, float offs,
                                         float qbase, float qstep,
                                         const unsigned* __restrict__ s_lut,
                                         unsigned& e_out, bool& flag) {
    unsigned bi = min(__float2uint_rz(fmaf(x, scale, offs)), (unsigned)(NB - 1));
    unsigned e = s_lut[bi];
    e_out = e;
    float cc = fmaf((float)(e & 0xFFFFu), qstep, qbase);
    float bw = __half2float(__ushort_as_half((unsigned short)(e >> 16)));
    flag = (bw != bw);                             // fp16 NaN sentinel
    return __saturatef(fmaf(bw, x, cc));           // FFMA.SAT; sat(NaN)=0 (dead)
}

__global__ void __launch_bounds__(NTHR, 4)
pwl_main(const float* __restrict__ x, float* __restrict__ out, int n, int K) {
    __shared__ unsigned s_lut[NB];
    __shared__ float4   s_side[MAXSID];
    __shared__ float    s_sx[MAXK], s_a[MAXK], s_b[MAXK];

    {   // stage LUT with uint4 loads
        const uint4* src = (const uint4*)g_lutU;
        uint4* dst = (uint4*)s_lut;
        for (int i = threadIdx.x; i < NB / 4; i += NTHR) dst[i] = src[i];
        if (threadIdx.x < MAXSID) s_side[threadIdx.x] = g_side[threadIdx.x];
        if (threadIdx.x < MAXK) {
            int i = threadIdx.x;
            s_sx[i] = g_sx[i]; s_a[i] = g_a[i]; s_b[i] = g_b[i];
        }
    }
    __syncthreads();

    const float scale = g_scale, offs = g_offs;
    const float qbase = g_qbase, qstep = g_qstep;
    const int n4 = n >> 2;
    const float4* __restrict__ x4 = (const float4*)x;
    float4* __restrict__ o4 = (float4*)out;
    const int stride = gridDim.x * NTHR;

    #pragma unroll 2
    for (int i = blockIdx.x * NTHR + threadIdx.x; i < n4; i += stride) {
        float4 v = x4[i];
        unsigned e0, e1, e2, e3;
        bool f0, f1, f2, f3;
        float y0 = pwl_dec(v.x, scale, offs, qbase, qstep, s_lut, e0, f0);
        float y1 = pwl_dec(v.y, scale, offs, qbase, qstep, s_lut, e1, f1);
        float y2 = pwl_dec(v.z, scale, offs, qbase, qstep, s_lut, e2, f2);
        float y3 = pwl_dec(v.w, scale, offs, qbase, qstep, s_lut, e3, f3);

        if (f0 | f1 | f2 | f3) {                   // hot branch, slim body
            float u0 = side_raw(f0, v.x, e0, y0, s_side);
            float u1 = side_raw(f1, v.y, e1, y1, s_side);
            float u2 = side_raw(f2, v.z, e2, y2, s_side);
            float u3 = side_raw(f3, v.w, e3, y3, s_side);
            if ((u0 != u0) | (u1 != u1) | (u2 != u2) | (u3 != u3)) {  // cold
                if (u0 != u0) u0 = search_eval(v.x, s_sx, s_a, s_b, K);
                if (u1 != u1) u1 = search_eval(v.y, s_sx, s_a, s_b, K);
                if (u2 != u2) u2 = search_eval(v.z, s_sx, s_a, s_b, K);
                if (u3 != u3) u3 = search_eval(v.w, s_sx, s_a, s_b, K);
            }
            // clean lanes: u == y (already saturated) -> idempotent
            y0 = __saturatef(u0);
            y1 = __saturatef(u1);
            y2 = __saturatef(u2);
            y3 = __saturatef(u3);
        }

        float4 r;
        r.x = y0; r.y = y1; r.z = y2; r.w = y3;
        o4[i] = r;
    }

    // Scalar tail
    int rem = n & 3;
    if (blockIdx.x == 0 && (int)threadIdx.x < rem) {
        int i = (n4 << 2) + threadIdx.x;
        float xv = x[i];
        unsigned e;
        bool fl;
        float y = pwl_dec(xv, scale, offs, qbase, qstep, s_lut, e, fl);
        if (fl) {
            float u = side_raw(true, xv, e, y, s_side);
            if (u != u) u = search_eval(xv, s_sx, s_a, s_b, K);
            y = __saturatef(u);
        }
        out[i] = y;
    }
}

// ---------------------------------------------------------------------------
extern "C" void kernel_launch(void* const* d_in, const int* in_sizes, int n_in,
                              void* d_out, int out_size) {
    const float* x      = (const float*)d_in[0];
    const float* xp     = (const float*)d_in[1];
    const float* slopes = (const float*)d_in[2];
    const float* biases = (const float*)d_in[3];
    int K = in_sizes[1];
    if (K > MAXK) K = MAXK;

    pwl_pre<<<PREBLK, PRETHR>>>(xp, slopes, biases, K);
    pwl_main<<<NBLK, NTHR>>>(x, (float*)d_out, out_size, K);
}